// round 7
// baseline (speedup 1.0000x reference)
#include <cuda_runtime.h>
#include <math.h>

// ConvLSTM T=16,B=4,Cin=32,HID=64,H=W=64, 3x3 SAME.
// Fused per-step conv(x)+conv(h)+LSTM pointwise with packed fma.rn.f32x2,
// register-budgeted: acc[8][2] (32 regs) + v[4][3] (24 regs).

#define T_   16
#define B_   4
#define CIN  32
#define HID  64
#define HH   64
#define WW   64
#define ICC  8
#define PROWS 34          // 32 + 2 halo rows
#define PCOLS 34          // 32 + 2 halo cols
#define PPAD  36          // padded col stride (8B-aligned pairs)

#define PATCH_FLOATS (ICC * PROWS * PPAD)
#define W_FLOATS     (ICC * 8 * 9 * 2)
#define SMEM_BYTES   ((PATCH_FLOATS + W_FLOATS) * 4)

typedef unsigned long long ull;

__device__ float g_c[B_ * HID * HH * WW];   // cell state (4 MB)

__device__ __forceinline__ float sigmoidf_(float v) {
    return 1.f / (1.f + __expf(-v));
}
__device__ __forceinline__ void fma2(ull& d, ull a, ull b) {
    asm("fma.rn.f32x2 %0, %1, %2, %0;" : "+l"(d) : "l"(a), "l"(b));
}
__device__ __forceinline__ ull pk2(float lo, float hi) {
    ull r;
    asm("mov.b64 %0, {%1, %2};" : "=l"(r) : "f"(lo), "f"(hi));
    return r;
}
__device__ __forceinline__ float plo(ull v) { return __uint_as_float((unsigned)v); }
__device__ __forceinline__ float phi(ull v) { return __uint_as_float((unsigned)(v >> 32)); }

__global__ __launch_bounds__(256, 2)
void convlstm_step(const float* __restrict__ x_t,     // [B, CIN, H, W]
                   const float* __restrict__ h_prev,  // [B, HID, H, W]
                   const float* __restrict__ w_x2h,   // [4*HID, CIN, 3, 3]
                   const float* __restrict__ w_h2h,   // [4*HID, HID, 3, 3]
                   const float* __restrict__ b_x2h,
                   const float* __restrict__ b_h2h,
                   float* __restrict__ h_out,         // [B, HID, H, W]
                   int first)
{
    extern __shared__ float smem[];
    float* patch = smem;                  // [ICC][PROWS][PPAD]
    float* wdup  = smem + PATCH_FLOATS;   // [ICC][8][9][2] duplicated pairs

    const int tid  = threadIdx.x;
    const int warp = tid >> 5;
    const int lane = tid & 31;
    const int ty   = tid >> 4;            // 0..15 -> rows 2ty, 2ty+1
    const int tx   = tid & 15;            // 0..15 -> cols 2tx, 2tx+1 (one pair)
    const int tile = blockIdx.x;          // 0..3 (2x2 tiles of 32x32)
    const int ty0  = (tile >> 1) * 32;
    const int tx0  = (tile & 1) * 32;
    const int hid_base = blockIdx.y * 2;  // 2 hid channels per block
    const int b = blockIdx.z;

    // acc[l][r]: l = gate*2 + jh, r = row 0/1. Each ull = pixel pair (2tx, 2tx+1).
    ull acc[8][2];
#pragma unroll
    for (int l = 0; l < 8; l++) {
        int oc = (l >> 1) * HID + hid_base + (l & 1);
        float bias = b_x2h[oc] + b_h2h[oc];
        ull bb = pk2(bias, bias);
        acc[l][0] = bb; acc[l][1] = bb;
    }

    const int icTotal = first ? CIN : (CIN + HID);

    for (int ic0 = 0; ic0 < icTotal; ic0 += ICC) {
        const float* src;
        const float* wsrc;
        int wnic, ch;
        if (ic0 < CIN) {
            src = x_t + (size_t)b * CIN * HH * WW;
            wsrc = w_x2h; wnic = CIN; ch = ic0;
        } else {
            src = h_prev + (size_t)b * HID * HH * WW;
            wsrc = w_h2h; wnic = HID; ch = ic0 - CIN;
        }

        // structured patch fill: job = (ic, row), warp handles jobs warp, warp+8, ...
        for (int job = warp; job < ICC * PROWS; job += 8) {
            int ic  = job / PROWS;
            int row = job - ic * PROWS;
            int gy  = ty0 - 1 + row;
            const float* gsrc = src + (size_t)(ch + ic) * HH * WW + gy * WW;
            float* dst = patch + ic * PROWS * PPAD + row * PPAD;
            bool rowok = (unsigned)gy < (unsigned)HH;
#pragma unroll
            for (int c0 = 0; c0 < PCOLS; c0 += 32) {
                int col = c0 + lane;
                if (col < PCOLS) {
                    int gx = tx0 - 1 + col;
                    float v = 0.f;
                    if (rowok && (unsigned)gx < (unsigned)WW) v = gsrc[gx];
                    dst[col] = v;
                }
            }
        }
        // weights: duplicated pairs
        for (int idx = tid; idx < ICC * 8 * 9; idx += 256) {
            int ic = idx / 72;
            int r  = idx - ic * 72;
            int l  = r / 9;
            int k  = r - l * 9;
            int oc = (l >> 1) * HID + hid_base + (l & 1);
            float w = wsrc[((size_t)oc * wnic + ch + ic) * 9 + k];
            wdup[(idx << 1)]     = w;
            wdup[(idx << 1) + 1] = w;
        }
        __syncthreads();

#pragma unroll
        for (int ic = 0; ic < ICC; ic++) {
            // v[r][s]: input rows 2ty+r (r=0..3), pair starting at col 2tx+s (s=0..2)
            ull v[4][3];
            const float* prow = patch + ic * PROWS * PPAD + (2 * ty) * PPAD + 2 * tx;
#pragma unroll
            for (int r = 0; r < 4; r++) {
                ull a = *(const ull*)(prow + r * PPAD);
                ull c = *(const ull*)(prow + r * PPAD + 2);
                v[r][0] = a;
                v[r][2] = c;
                v[r][1] = pk2(phi(a), plo(c));   // odd-offset pair via repack
            }
            const float* wp = wdup + ic * 144;
#pragma unroll
            for (int l = 0; l < 8; l++) {
#pragma unroll
                for (int ky = 0; ky < 3; ky++) {
#pragma unroll
                    for (int kx = 0; kx < 3; kx++) {
                        ull w2 = *(const ull*)(wp + l * 18 + (ky * 3 + kx) * 2);
                        fma2(acc[l][0], v[ky + 0][kx], w2);
                        fma2(acc[l][1], v[ky + 1][kx], w2);
                    }
                }
            }
        }
        __syncthreads();
    }

    // LSTM epilogue: gate order i, f, g, o
#pragma unroll
    for (int jh = 0; jh < 2; jh++) {
        const int hid = hid_base + jh;
#pragma unroll
        for (int r = 0; r < 2; r++) {
            const int y = ty0 + 2 * ty + r;
#pragma unroll
            for (int half = 0; half < 2; half++) {
                const int x = tx0 + 2 * tx + half;
                const size_t off = ((size_t)(b * HID + hid)) * HH * WW
                                 + (size_t)y * WW + x;
                float aI = half ? phi(acc[0 * 2 + jh][r]) : plo(acc[0 * 2 + jh][r]);
                float aF = half ? phi(acc[1 * 2 + jh][r]) : plo(acc[1 * 2 + jh][r]);
                float aG = half ? phi(acc[2 * 2 + jh][r]) : plo(acc[2 * 2 + jh][r]);
                float aO = half ? phi(acc[3 * 2 + jh][r]) : plo(acc[3 * 2 + jh][r]);
                float gi = sigmoidf_(aI);
                float gf = sigmoidf_(aF);
                float gg = tanhf(aG);
                float go = sigmoidf_(aO);
                float cold = first ? 0.f : g_c[off];
                float cn = gf * cold + gi * gg;
                g_c[off]   = cn;
                h_out[off] = go * tanhf(cn);
            }
        }
    }
}

extern "C" void kernel_launch(void* const* d_in, const int* in_sizes, int n_in,
                              void* d_out, int out_size)
{
    const float* x     = (const float*)d_in[0];
    const float* w_x2h = (const float*)d_in[1];
    const float* b_x2h = (const float*)d_in[2];
    const float* w_h2h = (const float*)d_in[3];
    const float* b_h2h = (const float*)d_in[4];
    float* out = (float*)d_out;

    cudaFuncSetAttribute(convlstm_step,
                         cudaFuncAttributeMaxDynamicSharedMemorySize, SMEM_BYTES);

    const size_t x_step = (size_t)B_ * CIN * HH * WW;
    const size_t h_step = (size_t)B_ * HID * HH * WW;

    dim3 grid(4, HID / 2, B_);   // 4 spatial tiles, 32 hid-groups, 4 batch
    for (int t = 0; t < T_; t++) {
        const float* x_t    = x + (size_t)t * x_step;
        const float* h_prev = (t == 0) ? x : out + (size_t)(t - 1) * h_step;
        float* h_out        = out + (size_t)t * h_step;
        convlstm_step<<<grid, 256, SMEM_BYTES>>>(x_t, h_prev, w_x2h, w_h2h,
                                                 b_x2h, b_h2h, h_out, t == 0 ? 1 : 0);
    }
}